// round 6
// baseline (speedup 1.0000x reference)
#include <cuda_runtime.h>
#include <math.h>

#define NCLS 6
#define TT 60
#define NBLK 64          // one block per batch; 3 scale-groups of 64 threads
#define NPART 192        // 3 scales * 64 batches partial slots (layout unchanged)

__device__ float g_part[NPART * 4];
__device__ unsigned int g_count = 0;   // arrival counter; last block resets to 0

__device__ __forceinline__ float bce_f(float x, float t) {
    // max(x,0) - x*t + log(1 + exp(-|x|)) (fast-math variant; err << 1e-3 tol)
    return fmaxf(x, 0.0f) - x * t + __logf(1.0f + __expf(-fabsf(x)));
}

__device__ __forceinline__ float iou_f(float px, float py, float pw, float ph,
                                       float tx, float ty, float tw, float th) {
    float x11 = px - pw * 0.5f, y11 = py - ph * 0.5f;
    float x12 = px + pw * 0.5f, y12 = py + ph * 0.5f;
    float x21 = tx - tw * 0.5f, y21 = ty - th * 0.5f;
    float x22 = tx + tw * 0.5f, y22 = ty + th * 0.5f;
    float iw = fmaxf(fminf(x12, x22) - fmaxf(x11, x21), 0.0f);
    float ih = fmaxf(fminf(y12, y22) - fmaxf(y11, y21), 0.0f);
    float inter = iw * ih;
    float a1 = (x12 - x11) * (y12 - y11);
    float a2 = (x22 - x21) * (y22 - y21);
    return inter / (a1 + a2 - inter + 1e-7f);
}

__global__ void __launch_bounds__(192)
det_loss_fused(const float* __restrict__ p3,
               const float* __restrict__ p4,
               const float* __restrict__ p5,
               const int*   __restrict__ tcls,
               const float* __restrict__ tbox,
               float* __restrict__ out) {
    const int b = blockIdx.x;            // batch
    const int t = threadIdx.x;           // 0..191
    const int scale = t >> 6;            // 0,1,2  (group of 64 threads)
    const int j     = t & 63;            // target index within group (active j<60)
    const int W = 160 >> scale;
    const float* __restrict__ pred = (scale == 0) ? p3 : ((scale == 1) ? p4 : p5);

    __shared__ int scell[3][64];
    __shared__ unsigned char sclsid[64];

    // Each thread loads its own target box (3 groups hit the same lines; L2 dedupes)
    float txv = 0.f, tyv = 0.f, twv = 0.f, thv = 0.f;
    if (j < TT) {
        const float4 tb = ((const float4*)tbox)[(size_t)b * TT + j];
        txv = tb.x; tyv = tb.y; twv = tb.z; thv = tb.w;
        int gx = (int)(txv * (float)W);  gx = min(max(gx, 0), W - 1);
        int gy = (int)(tyv * (float)W);  gy = min(max(gy, 0), W - 1);
        scell[scale][j] = gy * W + gx;
        if (scale == 0) sclsid[j] = (unsigned char)tcls[b * TT + j];
    }
    __syncthreads();

    float cls_sum = 0.0f, iou_sum = 0.0f, inner_sum = 0.0f, npos = 0.0f;

    if (j < TT) {
        const int mycell = scell[scale][j];

        // speculative gather — overlap the 10 scattered DRAM loads with the scan
        const int gy0 = mycell / W;
        const int gx0 = mycell - gy0 * W;
        const size_t HW  = (size_t)W * (size_t)W;
        const size_t off = (size_t)(b * 11) * HW + (size_t)gy0 * W + gx0;
        float cpred[NCLS];
        #pragma unroll
        for (int c = 0; c < NCLS; c++) cpred[c] = pred[off + (size_t)c * HW];
        const float px = pred[off + (size_t)7  * HW];
        const float py = pred[off + (size_t)8  * HW];
        const float pw = pred[off + (size_t)9  * HW];
        const float ph = pred[off + (size_t)10 * HW];

        // collision scan: last (highest index) target wins; cls mask ORs co-located
        unsigned mask = 0u;
        bool winner = true;
        #pragma unroll
        for (int j2 = 0; j2 < TT; j2++) {
            if (scell[scale][j2] == mycell) {
                mask |= 1u << sclsid[j2];
                if (j2 > j) winner = false;
            }
        }

        if (winner) {
            #pragma unroll
            for (int c = 0; c < NCLS; c++) {
                const float tv = ((mask >> c) & 1u) ? 1.0f : 0.0f;
                cls_sum += bce_f(cpred[c], tv);
            }
            const float iou   = iou_f(px, py, pw, ph, txv, tyv, twv, thv);
            const float inner = iou_f(px, py, pw * 0.7f, ph * 0.7f,
                                      txv, tyv, twv * 0.7f, thv * 0.7f);
            iou_sum   = 1.0f - iou;
            inner_sum = 1.0f - inner;
            npos      = 1.0f;
        }
    }

    // per-group (64-thread) reduce: 2 warps per group, ALL lanes participate
    const unsigned fullm = 0xFFFFFFFFu;
    #pragma unroll
    for (int s = 16; s > 0; s >>= 1) {
        cls_sum   += __shfl_down_sync(fullm, cls_sum,   s);
        iou_sum   += __shfl_down_sync(fullm, iou_sum,   s);
        inner_sum += __shfl_down_sync(fullm, inner_sum, s);
        npos      += __shfl_down_sync(fullm, npos,      s);
    }
    __shared__ float red[6][4];          // [warp 0..5][k]
    __shared__ bool s_is_last;
    const int wrp = t >> 5, lid = t & 31;
    if (lid == 0) {
        red[wrp][0] = cls_sum; red[wrp][1] = iou_sum;
        red[wrp][2] = inner_sum; red[wrp][3] = npos;
    }
    __syncthreads();

    // group leader (j==0 of each scale group) writes the 4 partials
    if (j == 0) {
        const int w0 = scale * 2;
        const int slot = (scale * 64 + b) * 4;
        g_part[slot + 0] = red[w0][0] + red[w0 + 1][0];
        g_part[slot + 1] = red[w0][1] + red[w0 + 1][1];
        g_part[slot + 2] = red[w0][2] + red[w0 + 1][2];
        g_part[slot + 3] = red[w0][3] + red[w0 + 1][3];
    }
    __syncthreads();                     // all 3 groups' STGs happen-before t0's fence

    if (t == 0) {
        __threadfence();                 // publish partials GPU-wide
        const unsigned prev = atomicAdd(&g_count, 1u);
        s_is_last = (prev == NBLK - 1u);
    }
    __syncthreads();

    if (!s_is_last) return;

    // ── last block: acquire, batched plain loads, fixed-order deterministic sum ──
    __threadfence();
    __shared__ float sums[12];
    if (t < 12) {
        const int s = t >> 2, k = t & 3;
        float a0 = 0.0f, a1 = 0.0f, a2 = 0.0f, a3 = 0.0f;
        const int base = (s * 64) * 4 + k;
        #pragma unroll
        for (int i = 0; i < 16; i++) {
            a0 += g_part[base + (i * 4 + 0) * 4];
            a1 += g_part[base + (i * 4 + 1) * 4];
            a2 += g_part[base + (i * 4 + 2) * 4];
            a3 += g_part[base + (i * 4 + 3) * 4];
        }
        sums[t] = (a0 + a1) + (a2 + a3);
    }
    __syncthreads();

    if (t == 0) {
        float cls_total = 0.0f, box_total = 0.0f;
        #pragma unroll
        for (int s2 = 0; s2 < 3; s2++) {
            const float np        = sums[s2 * 4 + 3];
            const float denom     = np + 1e-8f;
            const float cls_loss  = sums[s2 * 4 + 0] / denom;
            const float iou_term  = sums[s2 * 4 + 1] / denom;
            const float inner_t   = sums[s2 * 4 + 2] / denom;
            const float inner_iou = 0.5f * iou_term + 0.5f * inner_t;
            const float box_loss  = 0.5f * iou_term + 0.5f * inner_iou;
            cls_total += cls_loss;
            box_total += box_loss;
        }
        cls_total = cls_total / 3.0f;
        box_total = box_total / 3.0f;
        const float total = 0.5f * cls_total + 7.5f * box_total;
        out[0] = total;
        out[1] = cls_total;
        out[2] = box_total;
        g_count = 0;                     // reset for next graph replay
    }
}

extern "C" void kernel_launch(void* const* d_in, const int* in_sizes, int n_in,
                              void* d_out, int out_size) {
    const float* p3   = (const float*)d_in[0];
    const float* p4   = (const float*)d_in[1];
    const float* p5   = (const float*)d_in[2];
    const int*   tcls = (const int*)  d_in[3];
    const float* tbox = (const float*)d_in[4];
    float* out = (float*)d_out;

    det_loss_fused<<<NBLK, 192>>>(p3, p4, p5, tcls, tbox, out);
}

// round 7
// speedup vs baseline: 1.0060x; 1.0060x over previous
#include <cuda_runtime.h>
#include <math.h>

#define NCLS 6
#define TT 60
#define NBLK 64          // one block per batch; 3 scale-groups of 64 threads

// 12 global accumulators: [scale][k], k = {cls, iou, inner, npos}
__device__ float g_acc[12];
__device__ unsigned int g_count = 0;   // arrival counter; last block resets all

__device__ __forceinline__ float bce_f(float x, float t) {
    return fmaxf(x, 0.0f) - x * t + __logf(1.0f + __expf(-fabsf(x)));
}

__device__ __forceinline__ float iou_f(float px, float py, float pw, float ph,
                                       float tx, float ty, float tw, float th) {
    float x11 = px - pw * 0.5f, y11 = py - ph * 0.5f;
    float x12 = px + pw * 0.5f, y12 = py + ph * 0.5f;
    float x21 = tx - tw * 0.5f, y21 = ty - th * 0.5f;
    float x22 = tx + tw * 0.5f, y22 = ty + th * 0.5f;
    float iw = fmaxf(fminf(x12, x22) - fmaxf(x11, x21), 0.0f);
    float ih = fmaxf(fminf(y12, y22) - fmaxf(y11, y21), 0.0f);
    float inter = iw * ih;
    float a1 = (x12 - x11) * (y12 - y11);
    float a2 = (x22 - x21) * (y22 - y21);
    return inter / (a1 + a2 - inter + 1e-7f);
}

__global__ void __launch_bounds__(192)
det_loss_fused(const float* __restrict__ p3,
               const float* __restrict__ p4,
               const float* __restrict__ p5,
               const int*   __restrict__ tcls,
               const float* __restrict__ tbox,
               float* __restrict__ out) {
    const int b = blockIdx.x;            // batch
    const int t = threadIdx.x;           // 0..191
    const int scale = t >> 6;            // 0,1,2  (group of 64 threads)
    const int j     = t & 63;            // target index within group (active j<60)
    const int W = 160 >> scale;
    const float* __restrict__ pred = (scale == 0) ? p3 : ((scale == 1) ? p4 : p5);

    __shared__ int scell[3][64];
    __shared__ unsigned char sclsid[64];

    float txv = 0.f, tyv = 0.f, twv = 0.f, thv = 0.f;
    if (j < TT) {
        const float4 tb = ((const float4*)tbox)[(size_t)b * TT + j];
        txv = tb.x; tyv = tb.y; twv = tb.z; thv = tb.w;
        int gx = (int)(txv * (float)W);  gx = min(max(gx, 0), W - 1);
        int gy = (int)(tyv * (float)W);  gy = min(max(gy, 0), W - 1);
        scell[scale][j] = gy * W + gx;
        if (scale == 0) sclsid[j] = (unsigned char)tcls[b * TT + j];
    }
    __syncthreads();

    float cls_sum = 0.0f, iou_sum = 0.0f, inner_sum = 0.0f, npos = 0.0f;

    if (j < TT) {
        const int mycell = scell[scale][j];

        // speculative gather — overlap the 10 scattered DRAM loads with the scan
        const int gy0 = mycell / W;
        const int gx0 = mycell - gy0 * W;
        const size_t HW  = (size_t)W * (size_t)W;
        const size_t off = (size_t)(b * 11) * HW + (size_t)gy0 * W + gx0;
        float cpred[NCLS];
        #pragma unroll
        for (int c = 0; c < NCLS; c++) cpred[c] = pred[off + (size_t)c * HW];
        const float px = pred[off + (size_t)7  * HW];
        const float py = pred[off + (size_t)8  * HW];
        const float pw = pred[off + (size_t)9  * HW];
        const float ph = pred[off + (size_t)10 * HW];

        // collision scan: last (highest index) target wins; cls mask ORs co-located
        unsigned mask = 0u;
        bool winner = true;
        #pragma unroll
        for (int j2 = 0; j2 < TT; j2++) {
            if (scell[scale][j2] == mycell) {
                mask |= 1u << sclsid[j2];
                if (j2 > j) winner = false;
            }
        }

        if (winner) {
            #pragma unroll
            for (int c = 0; c < NCLS; c++) {
                const float tv = ((mask >> c) & 1u) ? 1.0f : 0.0f;
                cls_sum += bce_f(cpred[c], tv);
            }
            const float iou   = iou_f(px, py, pw, ph, txv, tyv, twv, thv);
            const float inner = iou_f(px, py, pw * 0.7f, ph * 0.7f,
                                      txv, tyv, twv * 0.7f, thv * 0.7f);
            iou_sum   = 1.0f - iou;
            inner_sum = 1.0f - inner;
            npos      = 1.0f;
        }
    }

    // per-group (64-thread) reduce: 2 warps per group, ALL lanes participate
    const unsigned fullm = 0xFFFFFFFFu;
    #pragma unroll
    for (int s = 16; s > 0; s >>= 1) {
        cls_sum   += __shfl_down_sync(fullm, cls_sum,   s);
        iou_sum   += __shfl_down_sync(fullm, iou_sum,   s);
        inner_sum += __shfl_down_sync(fullm, inner_sum, s);
        npos      += __shfl_down_sync(fullm, npos,      s);
    }
    __shared__ float red[6][4];          // [warp 0..5][k]
    __shared__ bool s_is_last;
    const int wrp = t >> 5, lid = t & 31;
    if (lid == 0) {
        red[wrp][0] = cls_sum; red[wrp][1] = iou_sum;
        red[wrp][2] = inner_sum; red[wrp][3] = npos;
    }
    __syncthreads();

    // 12 threads (one per (scale,k)) fire the global atomic accumulation
    if (t < 12) {
        const int s = t >> 2, k = t & 3;
        const int w0 = s * 2;
        atomicAdd(&g_acc[t], red[w0][k] + red[w0 + 1][k]);
    }
    __syncthreads();                     // all 12 atomics issued before arrival

    if (t == 0) {
        __threadfence();                 // value atomics visible before counter bump
        const unsigned prev = atomicAdd(&g_count, 1u);
        s_is_last = (prev == NBLK - 1u);
    }
    __syncthreads();

    if (!s_is_last) return;

    // ── last block: fence, read the 12 accumulators, finish, reset ──
    __threadfence();
    __shared__ float sums[12];
    if (t < 12) sums[t] = g_acc[t];
    __syncthreads();

    if (t == 0) {
        float cls_total = 0.0f, box_total = 0.0f;
        #pragma unroll
        for (int s2 = 0; s2 < 3; s2++) {
            const float np        = sums[s2 * 4 + 3];
            const float denom     = np + 1e-8f;
            const float cls_loss  = sums[s2 * 4 + 0] / denom;
            const float iou_term  = sums[s2 * 4 + 1] / denom;
            const float inner_t   = sums[s2 * 4 + 2] / denom;
            const float inner_iou = 0.5f * iou_term + 0.5f * inner_t;  // (1-INNER_W), INNER_W
            const float box_loss  = 0.5f * iou_term + 0.5f * inner_iou;
            cls_total += cls_loss;
            box_total += box_loss;
        }
        cls_total = cls_total / 3.0f;
        box_total = box_total / 3.0f;
        const float total = 0.5f * cls_total + 7.5f * box_total;
        out[0] = total;
        out[1] = cls_total;
        out[2] = box_total;
    }
    // reset accumulators + counter for the next graph replay
    if (t < 12) g_acc[t] = 0.0f;
    if (t == 0) { __threadfence(); g_count = 0; }
}

extern "C" void kernel_launch(void* const* d_in, const int* in_sizes, int n_in,
                              void* d_out, int out_size) {
    const float* p3   = (const float*)d_in[0];
    const float* p4   = (const float*)d_in[1];
    const float* p5   = (const float*)d_in[2];
    const int*   tcls = (const int*)  d_in[3];
    const float* tbox = (const float*)d_in[4];
    float* out = (float*)d_out;

    det_loss_fused<<<NBLK, 192>>>(p3, p4, p5, tcls, tbox, out);
}